// round 2
// baseline (speedup 1.0000x reference)
#include <cuda_runtime.h>
#include <cuda_bf16.h>
#include <math.h>

#define FULLMASK 0xFFFFFFFFu
#define NW 8   // warps per block (one matrix per warp)

__device__ double g_acc;

__device__ __forceinline__ float warp_sum(float v) {
    v += __shfl_xor_sync(FULLMASK, v, 16);
    v += __shfl_xor_sync(FULLMASK, v, 8);
    v += __shfl_xor_sync(FULLMASK, v, 4);
    v += __shfl_xor_sync(FULLMASK, v, 2);
    v += __shfl_xor_sync(FULLMASK, v, 1);
    return v;
}

__global__ void rdl_init() { g_acc = 0.0; }

__global__ void rdl_fin(float* out, int B) {
    out[0] = (float)(g_acc / (double)B);
}

__global__ __launch_bounds__(NW * 32)
void rdl_main(const float* __restrict__ X, const float* __restrict__ Y, int B) {
    const int lane = threadIdx.x & 31;
    const int wid  = threadIdx.x >> 5;
    const int mat  = blockIdx.x * NW + wid;

    __shared__ float Bs[NW][32][33];   // per-warp transpose / diag buffer
    __shared__ float wsum[NW];

    float contrib = 0.0f;

    if (mat < B) {
        const float* xb = X + (size_t)mat * 1024;
        const float* yb = Y + (size_t)mat * 1024;

        // ---- load Y column `lane` (== row `lane`, Y symmetric). Coalesced. ----
        float Lr[32];
        #pragma unroll
        for (int c = 0; c < 32; ++c) Lr[c] = yb[c * 32 + lane];

        // ---- Cholesky in registers (thread i holds row i). Diagonal stores 1/L[k][k]. ----
        #pragma unroll
        for (int k = 0; k < 32; ++k) {
            float s = Lr[k];
            #pragma unroll
            for (int m = 0; m < k; ++m) {
                float lkm = __shfl_sync(FULLMASK, Lr[m], k);
                s = fmaf(-Lr[m], lkm, s);
            }
            float skk = __shfl_sync(FULLMASK, s, k);
            float inv = rsqrtf(skk);
            Lr[k] = (lane == k) ? inv : s * inv;
        }

        // ---- load X column `lane`; forward solve L Z = X (column-wise) ----
        float z[32];
        #pragma unroll
        for (int c = 0; c < 32; ++c) z[c] = xb[c * 32 + lane];
        #pragma unroll
        for (int i = 0; i < 32; ++i) {
            float s = z[i];
            #pragma unroll
            for (int k = 0; k < i; ++k)
                s = fmaf(-__shfl_sync(FULLMASK, Lr[k], i), z[k], s);
            z[i] = s * __shfl_sync(FULLMASK, Lr[i], i);
        }

        // ---- transpose Z via shared: Bs = Z^T ----
        #pragma unroll
        for (int i = 0; i < 32; ++i) Bs[wid][lane][i] = z[i];
        __syncwarp();

        // ---- forward solve L M = Z^T  ->  M = L^{-1} X L^{-T} (SPD, similar to y^{-1}x) ----
        float m[32];
        #pragma unroll
        for (int i = 0; i < 32; ++i) {
            float s = Bs[wid][i][lane];
            #pragma unroll
            for (int k = 0; k < i; ++k)
                s = fmaf(-__shfl_sync(FULLMASK, Lr[k], i), m[k], s);
            m[i] = s * __shfl_sync(FULLMASK, Lr[i], i);
        }
        __syncwarp();

        // ---- Householder tridiagonalization (rows in registers, shfl broadcasts) ----
        float e[31];
        #pragma unroll
        for (int k = 0; k < 30; ++k) {
            float xk    = (lane > k) ? m[k] : 0.0f;
            float alpha = __shfl_sync(FULLMASK, m[k], k + 1);
            float t     = (lane > k + 1) ? xk * xk : 0.0f;
            float sigma = warp_sum(t);                     // sum of squares below alpha

            float mu    = sqrtf(fmaf(alpha, alpha, sigma));
            float beta  = (alpha >= 0.0f) ? -mu : mu;
            float tau   = (beta - alpha) / beta;
            float scale = 1.0f / (alpha - beta);
            float v     = (lane == k + 1) ? 1.0f
                        : ((lane > k + 1) ? xk * scale : 0.0f);
            if (sigma <= 1e-12f) {                          // warp-uniform branch
                beta = alpha; tau = 0.0f; v = 0.0f;
            }
            e[k] = beta;

            // p = tau * A v
            float p = 0.0f;
            #pragma unroll
            for (int j = 0; j < 32; ++j)
                p = fmaf(m[j], __shfl_sync(FULLMASK, v, j), p);
            p *= tau;

            // w = p - (tau/2) (p.v) v   [tau factor was the round-1 bug]
            float dot = tau * warp_sum(p * v);
            float w   = fmaf(-0.5f * dot, v, p);

            // A <- A - v w^T - w v^T
            #pragma unroll
            for (int j = 0; j < 32; ++j) {
                float vj = __shfl_sync(FULLMASK, v, j);
                float wj = __shfl_sync(FULLMASK, w, j);
                m[j] = fmaf(-v, wj, fmaf(-w, vj, m[j]));
            }
        }
        e[30] = __shfl_sync(FULLMASK, m[30], 31);

        // ---- extract diagonal via shared (dynamic self-index not possible in regs) ----
        #pragma unroll
        for (int i = 0; i < 32; ++i) Bs[wid][i][lane] = m[i];
        __syncwarp();
        float d[32], e2[31];
        #pragma unroll
        for (int i = 0; i < 32; ++i) d[i] = Bs[wid][i][i];   // broadcast LDS
        #pragma unroll
        for (int i = 0; i < 31; ++i) e2[i] = e[i] * e[i];

        // ---- Gershgorin bounds (redundant per-lane, all in regs) ----
        float glo = d[0] - fabsf(e[0]);
        float ghi = d[0] + fabsf(e[0]);
        #pragma unroll
        for (int i = 1; i < 31; ++i) {
            float r = fabsf(e[i - 1]) + fabsf(e[i]);
            glo = fminf(glo, d[i] - r);
            ghi = fmaxf(ghi, d[i] + r);
        }
        glo = fminf(glo, d[31] - fabsf(e[30]));
        ghi = fmaxf(ghi, d[31] + fabsf(e[30]));
        float span = ghi - glo;
        float lo = glo - 1e-4f * span - 1e-6f;
        float hi = ghi + 1e-4f * span + 1e-6f;

        // ---- Sturm bisection: lane j computes the j-th smallest eigenvalue ----
        const int jj = lane;
        #pragma unroll 1
        for (int it = 0; it < 26; ++it) {
            float mid = 0.5f * (lo + hi);
            float q = d[0] - mid;
            int cnt = (q < 0.0f) ? 1 : 0;
            #pragma unroll
            for (int i = 1; i < 32; ++i) {
                float qg = (fabsf(q) < 1e-20f) ? -1e-20f : q;
                q = d[i] - mid - __fdividef(e2[i - 1], qg);
                cnt += (q < 0.0f) ? 1 : 0;
            }
            if (cnt <= jj) lo = mid; else hi = mid;
        }
        float lam = fmaxf(0.5f * (lo + hi), 1e-20f);
        float lg  = logf(lam);
        contrib   = sqrtf(warp_sum(lg * lg));   // d_b, same in all lanes
    }

    if (lane == 0) wsum[wid] = contrib;
    __syncthreads();
    if (threadIdx.x == 0) {
        double s = 0.0;
        #pragma unroll
        for (int w = 0; w < NW; ++w) s += (double)wsum[w];
        atomicAdd(&g_acc, s);
    }
}

extern "C" void kernel_launch(void* const* d_in, const int* in_sizes, int n_in,
                              void* d_out, int out_size) {
    const float* x = (const float*)d_in[0];
    const float* y = (const float*)d_in[1];
    int B = in_sizes[0] / 1024;          // 32*32 elements per matrix
    float* out = (float*)d_out;

    rdl_init<<<1, 1>>>();
    int blocks = (B + NW - 1) / NW;
    rdl_main<<<blocks, NW * 32>>>(x, y, B);
    rdl_fin<<<1, 1>>>(out, B);
}

// round 3
// speedup vs baseline: 1.5726x; 1.5726x over previous
#include <cuda_runtime.h>
#include <cuda_bf16.h>
#include <math.h>

#define FULLMASK 0xFFFFFFFFu
#define NW 4   // warps per block (one matrix per warp)

__device__ double g_acc;

__device__ __forceinline__ float warp_sum(float v) {
    v += __shfl_xor_sync(FULLMASK, v, 16);
    v += __shfl_xor_sync(FULLMASK, v, 8);
    v += __shfl_xor_sync(FULLMASK, v, 4);
    v += __shfl_xor_sync(FULLMASK, v, 2);
    v += __shfl_xor_sync(FULLMASK, v, 1);
    return v;
}

// raw approximate reciprocal: sign-correct for +-0 -> +-inf, inf -> 0.
// Only used inside bisection where just the SIGN of the recurrence matters.
__device__ __forceinline__ float frcp(float x) {
    float r; asm("rcp.approx.f32 %0, %1;" : "=f"(r) : "f"(x)); return r;
}

__global__ void rdl_init() { g_acc = 0.0; }

__global__ void rdl_fin(float* out, int B) {
    out[0] = (float)(g_acc / (double)B);
}

__global__ __launch_bounds__(NW * 32)
void rdl_main(const float* __restrict__ X, const float* __restrict__ Y, int B) {
    const int lane = threadIdx.x & 31;
    const int wid  = threadIdx.x >> 5;
    const int mat  = blockIdx.x * NW + wid;

    __shared__ float Bs[NW][32][33];   // per-warp transpose buffer + v/w broadcast rows
    __shared__ float wsum[NW];

    float contrib = 0.0f;

    if (mat < B) {
        const float* xb = X + (size_t)mat * 1024;
        const float* yb = Y + (size_t)mat * 1024;

        // ---- load Y column `lane` (== row, Y symmetric). Coalesced. ----
        float Lr[32];
        #pragma unroll
        for (int c = 0; c < 32; ++c) Lr[c] = yb[c * 32 + lane];

        // ---- Cholesky in registers (thread i holds row i). Diag stores 1/L[k][k]. ----
        #pragma unroll
        for (int k = 0; k < 32; ++k) {
            float s = Lr[k];
            #pragma unroll
            for (int m = 0; m < k; ++m) {
                float lkm = __shfl_sync(FULLMASK, Lr[m], k);
                s = fmaf(-Lr[m], lkm, s);
            }
            float skk = __shfl_sync(FULLMASK, s, k);
            float inv = rsqrtf(skk);
            Lr[k] = (lane == k) ? inv : s * inv;
        }

        // ---- load X column `lane`; forward solve L Z = X ----
        float z[32];
        #pragma unroll
        for (int c = 0; c < 32; ++c) z[c] = xb[c * 32 + lane];
        #pragma unroll
        for (int i = 0; i < 32; ++i) {
            float s = z[i];
            #pragma unroll
            for (int k = 0; k < i; ++k)
                s = fmaf(-__shfl_sync(FULLMASK, Lr[k], i), z[k], s);
            z[i] = s * __shfl_sync(FULLMASK, Lr[i], i);
        }

        // ---- transpose Z via shared: Bs = Z^T ----
        #pragma unroll
        for (int i = 0; i < 32; ++i) Bs[wid][lane][i] = z[i];
        __syncwarp();

        // ---- forward solve L M = Z^T  ->  M = L^{-1} X L^{-T} ----
        float m[32];
        #pragma unroll
        for (int i = 0; i < 32; ++i) {
            float s = Bs[wid][i][lane];
            #pragma unroll
            for (int k = 0; k < i; ++k)
                s = fmaf(-__shfl_sync(FULLMASK, Lr[k], i), m[k], s);
            m[i] = s * __shfl_sync(FULLMASK, Lr[i], i);
        }
        __syncwarp();   // Bs rows 0/1 are reused below

        // ---- Householder tridiagonalization ----
        // Range-limited trailing update (j >= k+1): rows 0..k are frozen, their
        // diagonals final. v/w broadcast via shared (LDS pipe), reductions via shfl.
        float* v_sh = &Bs[wid][0][0];
        float* w_sh = &Bs[wid][1][0];
        float e[31];
        #pragma unroll
        for (int k = 0; k < 30; ++k) {
            float xk    = (lane > k) ? m[k] : 0.0f;
            float alpha = __shfl_sync(FULLMASK, m[k], k + 1);
            float t     = (lane > k + 1) ? xk * xk : 0.0f;
            float sigma = warp_sum(t);

            float mu    = sqrtf(fmaf(alpha, alpha, sigma));
            float beta  = (alpha >= 0.0f) ? -mu : mu;
            float tau   = __fdividef(beta - alpha, beta);
            float scale = __fdividef(1.0f, alpha - beta);
            float v     = (lane == k + 1) ? 1.0f
                        : ((lane > k + 1) ? xk * scale : 0.0f);
            if (sigma <= 1e-12f) {       // warp-uniform
                beta = alpha; tau = 0.0f; v = 0.0f;
            }
            e[k] = beta;

            __syncwarp();                 // prior update's reads of v_sh/w_sh done
            v_sh[lane] = v;
            __syncwarp();

            // p = tau * A v  (v_j = 0 for j <= k)
            float p = 0.0f;
            #pragma unroll
            for (int j = k + 1; j < 32; ++j)
                p = fmaf(m[j], v_sh[j], p);
            p *= tau;

            // w = p - (tau/2)(p.v) v
            float dot = tau * warp_sum(p * v);
            float w   = fmaf(-0.5f * dot, v, p);
            w_sh[lane] = w;
            __syncwarp();

            // trailing rows only: A <- A - v w^T - w v^T
            #pragma unroll
            for (int j = k + 1; j < 32; ++j)
                m[j] = fmaf(-v, w_sh[j], fmaf(-w, v_sh[j], m[j]));
        }
        e[30] = __shfl_sync(FULLMASK, m[30], 31);

        // ---- diagonal straight from registers via shfl ----
        float d[32], e2[31];
        #pragma unroll
        for (int i = 0; i < 32; ++i) d[i] = __shfl_sync(FULLMASK, m[i], i);
        #pragma unroll
        for (int i = 0; i < 31; ++i) e2[i] = fmaxf(e[i] * e[i], 1e-28f);

        // ---- Gershgorin bounds (per-lane redundant, registers only) ----
        float glo = d[0] - fabsf(e[0]);
        float ghi = d[0] + fabsf(e[0]);
        #pragma unroll
        for (int i = 1; i < 31; ++i) {
            float r = fabsf(e[i - 1]) + fabsf(e[i]);
            glo = fminf(glo, d[i] - r);
            ghi = fmaxf(ghi, d[i] + r);
        }
        glo = fminf(glo, d[31] - fabsf(e[30]));
        ghi = fmaxf(ghi, d[31] + fabsf(e[30]));
        float span = ghi - glo;
        float lo = glo - 1e-4f * span - 1e-6f;
        float hi = ghi + 1e-4f * span + 1e-6f;

        // ---- Sturm bisection: lane j isolates the j-th smallest eigenvalue.
        // Division-by-sign via rcp.approx (e2 floored > 0, so no 0*inf NaN;
        // q=+-0 -> -+inf keeps the count consistent). Sign count on ALU pipe.
        #pragma unroll 1
        for (int it = 0; it < 24; ++it) {
            float mid = 0.5f * (lo + hi);
            float q   = d[0] - mid;
            int   c   = __float_as_int(q) >> 31;          // -1 per negative q
            #pragma unroll
            for (int i = 1; i < 32; ++i) {
                q  = fmaf(-e2[i - 1], frcp(q), d[i] - mid);
                c += __float_as_int(q) >> 31;
            }
            bool up = (c + lane >= 0);                    // count(<mid) <= lane
            lo = up ? mid : lo;
            hi = up ? hi  : mid;
        }
        float lam = fmaxf(0.5f * (lo + hi), 1e-20f);
        float lg  = logf(lam);
        contrib   = sqrtf(warp_sum(lg * lg));   // same in all lanes
    }

    if (lane == 0) wsum[wid] = contrib;
    __syncthreads();
    if (threadIdx.x == 0) {
        double s = 0.0;
        #pragma unroll
        for (int w = 0; w < NW; ++w) s += (double)wsum[w];
        atomicAdd(&g_acc, s);
    }
}

extern "C" void kernel_launch(void* const* d_in, const int* in_sizes, int n_in,
                              void* d_out, int out_size) {
    const float* x = (const float*)d_in[0];
    const float* y = (const float*)d_in[1];
    int B = in_sizes[0] / 1024;          // 32*32 elements per matrix
    float* out = (float*)d_out;

    rdl_init<<<1, 1>>>();
    int blocks = (B + NW - 1) / NW;
    rdl_main<<<blocks, NW * 32>>>(x, y, B);
    rdl_fin<<<1, 1>>>(out, B);
}

// round 4
// speedup vs baseline: 1.6228x; 1.0319x over previous
#include <cuda_runtime.h>
#include <cuda_bf16.h>
#include <math.h>

#define FULLMASK 0xFFFFFFFFu
#define NW 4              // warps per block, one matrix per warp
#define BITERS 22         // bisection iterations

__device__ double g_acc;

__device__ __forceinline__ float warp_sum(float v) {
    v += __shfl_xor_sync(FULLMASK, v, 16);
    v += __shfl_xor_sync(FULLMASK, v, 8);
    v += __shfl_xor_sync(FULLMASK, v, 4);
    v += __shfl_xor_sync(FULLMASK, v, 2);
    v += __shfl_xor_sync(FULLMASK, v, 1);
    return v;
}

// raw approximate reciprocal: sign-correct (+-0 -> +-inf, inf -> -+0).
// Used only where the SIGN of the Sturm recurrence matters.
__device__ __forceinline__ float frcp(float x) {
    float r; asm("rcp.approx.f32 %0, %1;" : "=f"(r) : "f"(x)); return r;
}

__global__ void rdl_init() { g_acc = 0.0; }
__global__ void rdl_fin(float* out, int B) { out[0] = (float)(g_acc / (double)B); }

__global__ __launch_bounds__(NW * 32)
void rdl_main(const float* __restrict__ X, const float* __restrict__ Y, int B) {
    const int lane = threadIdx.x & 31;
    const int wid  = threadIdx.x >> 5;
    const int mat  = blockIdx.x * NW + wid;

    // Lsh: lower-tri L (diag holds 1/L[k][k]); stride 36 -> rows 16B-aligned
    // (column writes are 4-way bank-conflicted, reads are float4 broadcasts).
    __shared__ float Lsh[NW][32][36];
    __shared__ float Bs [NW][32][33];   // transpose buffer; rows 0 & 4-5 reused for v / (v,w)
    __shared__ float wsum[NW];

    float contrib = 0.0f;

    if (mat < B) {
        const float* xb = X + (size_t)mat * 1024;
        const float* yb = Y + (size_t)mat * 1024;

        // ---- prefetch X column `lane` (hides DRAM behind Cholesky) ----
        float xr[32];
        #pragma unroll
        for (int c = 0; c < 32; ++c) xr[c] = xb[c * 32 + lane];

        // ---- load Y column `lane` (== row, symmetric) ----
        float Lr[32];
        #pragma unroll
        for (int c = 0; c < 32; ++c) Lr[c] = yb[c * 32 + lane];

        // ---- Cholesky (thread=row, shfl broadcasts); store L column-wise to shared ----
        #pragma unroll
        for (int k = 0; k < 32; ++k) {
            float s = Lr[k];
            #pragma unroll
            for (int mm = 0; mm < k; ++mm) {
                float lkm = __shfl_sync(FULLMASK, Lr[mm], k);
                s = fmaf(-Lr[mm], lkm, s);
            }
            float skk = __shfl_sync(FULLMASK, s, k);
            float inv = rsqrtf(skk);
            float val = (lane == k) ? inv : s * inv;
            Lr[k] = val;
            Lsh[wid][lane][k] = val;       // column store (4-way conflict, cheap)
        }
        __syncwarp();

        // ---- forward solve L Z = X, thread = column, in-place on xr.
        //      Row i of L read as float4 BROADCASTS; diag component == 1/L[i][i]. ----
        #pragma unroll
        for (int i = 0; i < 32; ++i) {
            float s = xr[i];
            #pragma unroll
            for (int g = 0; g * 4 <= i; ++g) {
                float4 Lv = *(const float4*)&Lsh[wid][i][g * 4];
                if (g*4+0 < i) s = fmaf(-Lv.x, xr[g*4+0], s); else if (g*4+0 == i) s *= Lv.x;
                if (g*4+1 < i) s = fmaf(-Lv.y, xr[g*4+1], s); else if (g*4+1 == i) s *= Lv.y;
                if (g*4+2 < i) s = fmaf(-Lv.z, xr[g*4+2], s); else if (g*4+2 == i) s *= Lv.z;
                if (g*4+3 < i) s = fmaf(-Lv.w, xr[g*4+3], s); else if (g*4+3 == i) s *= Lv.w;
            }
            xr[i] = s;
        }

        // ---- transpose Z ----
        #pragma unroll
        for (int i = 0; i < 32; ++i) Bs[wid][lane][i] = xr[i];
        __syncwarp();

        // ---- forward solve L M = Z^T  ->  M = L^{-1} X L^{-T} ----
        float m[32];
        #pragma unroll
        for (int i = 0; i < 32; ++i) {
            float s = Bs[wid][i][lane];
            #pragma unroll
            for (int g = 0; g * 4 <= i; ++g) {
                float4 Lv = *(const float4*)&Lsh[wid][i][g * 4];
                if (g*4+0 < i) s = fmaf(-Lv.x, m[g*4+0], s); else if (g*4+0 == i) s *= Lv.x;
                if (g*4+1 < i) s = fmaf(-Lv.y, m[g*4+1], s); else if (g*4+1 == i) s *= Lv.y;
                if (g*4+2 < i) s = fmaf(-Lv.z, m[g*4+2], s); else if (g*4+2 == i) s *= Lv.z;
                if (g*4+3 < i) s = fmaf(-Lv.w, m[g*4+3], s); else if (g*4+3 == i) s *= Lv.w;
            }
            m[i] = s;
        }
        __syncwarp();

        // ---- Householder tridiagonalization, range-limited trailing update.
        //      v broadcast as float4; (v,w) interleaved float2 read as float4. ----
        float*  v_sh = &Bs[wid][0][0];            // 16B aligned
        float2* vw   = (float2*)&Bs[wid][4][0];   // offset 528B, 16B aligned
        float e[31];
        #pragma unroll
        for (int k = 0; k < 30; ++k) {
            float xk    = (lane > k) ? m[k] : 0.0f;
            float alpha = __shfl_sync(FULLMASK, m[k], k + 1);
            float sigma = warp_sum((lane > k + 1) ? xk * xk : 0.0f);

            float mu    = sqrtf(fmaf(alpha, alpha, sigma));
            float beta  = (alpha >= 0.0f) ? -mu : mu;
            float tau   = __fdividef(beta - alpha, beta);
            float scale = __fdividef(1.0f, alpha - beta);
            float v     = (lane == k + 1) ? 1.0f
                        : ((lane > k + 1) ? xk * scale : 0.0f);
            if (sigma <= 1e-12f) { beta = alpha; tau = 0.0f; v = 0.0f; }  // warp-uniform
            e[k] = beta;

            v_sh[lane] = v;
            __syncwarp();

            // p = tau * A v   (v_j == 0 for j <= k makes float4 over-read exact)
            float p = 0.0f;
            #pragma unroll
            for (int g = (k + 1) & ~3; g < 32; g += 4) {
                float4 vv = *(const float4*)&v_sh[g];
                p = fmaf(m[g+0], vv.x, p);
                p = fmaf(m[g+1], vv.y, p);
                p = fmaf(m[g+2], vv.z, p);
                p = fmaf(m[g+3], vv.w, p);
            }
            p *= tau;

            float dot = tau * warp_sum(p * v);
            float w   = fmaf(-0.5f * dot, v, p);
            vw[lane]  = make_float2(v, w);
            __syncwarp();

            // trailing update: A <- A - v w^T - w v^T  (2 columns per LDS.128)
            #pragma unroll
            for (int g = (k + 1) & ~1; g < 32; g += 2) {
                float4 t = *(const float4*)&vw[g];   // {v_g, w_g, v_g1, w_g1}
                m[g+0] = fmaf(-v, t.y, fmaf(-w, t.x, m[g+0]));
                m[g+1] = fmaf(-v, t.w, fmaf(-w, t.z, m[g+1]));
            }
        }
        e[30] = __shfl_sync(FULLMASK, m[30], 31);

        // ---- diagonal via shfl ----
        float d[32], e2[31];
        #pragma unroll
        for (int i = 0; i < 32; ++i) d[i] = __shfl_sync(FULLMASK, m[i], i);
        #pragma unroll
        for (int i = 0; i < 31; ++i) e2[i] = fmaxf(e[i] * e[i], 1e-28f);

        // ---- Gershgorin bounds ----
        float glo = d[0] - fabsf(e[0]);
        float ghi = d[0] + fabsf(e[0]);
        #pragma unroll
        for (int i = 1; i < 31; ++i) {
            float r = fabsf(e[i - 1]) + fabsf(e[i]);
            glo = fminf(glo, d[i] - r);
            ghi = fmaxf(ghi, d[i] + r);
        }
        glo = fminf(glo, d[31] - fabsf(e[30]));
        ghi = fmaxf(ghi, d[31] + fabsf(e[30]));
        float span = ghi - glo;
        float lo = glo - 1e-4f * span - 1e-6f;
        float hi = ghi + 1e-4f * span + 1e-6f;

        // ---- Sturm bisection: lane j isolates j-th smallest eigenvalue ----
        #pragma unroll 1
        for (int it = 0; it < BITERS; ++it) {
            float mid = 0.5f * (lo + hi);
            float q   = d[0] - mid;
            int   c   = __float_as_int(q) >> 31;      // -1 per negative pivot
            #pragma unroll
            for (int i = 1; i < 32; ++i) {
                q  = fmaf(-e2[i - 1], frcp(q), d[i] - mid);
                c += __float_as_int(q) >> 31;
            }
            bool up = (c + lane >= 0);                // count(<mid) <= lane
            lo = up ? mid : lo;
            hi = up ? hi  : mid;
        }
        float lam = fmaxf(0.5f * (lo + hi), 1e-20f);
        float lg  = logf(lam);
        contrib   = sqrtf(warp_sum(lg * lg));
    }

    if (lane == 0) wsum[wid] = contrib;
    __syncthreads();
    if (threadIdx.x == 0) {
        double s = 0.0;
        #pragma unroll
        for (int w = 0; w < NW; ++w) s += (double)wsum[w];
        atomicAdd(&g_acc, s);
    }
}

extern "C" void kernel_launch(void* const* d_in, const int* in_sizes, int n_in,
                              void* d_out, int out_size) {
    const float* x = (const float*)d_in[0];
    const float* y = (const float*)d_in[1];
    int B = in_sizes[0] / 1024;
    float* out = (float*)d_out;

    rdl_init<<<1, 1>>>();
    int blocks = (B + NW - 1) / NW;
    rdl_main<<<blocks, NW * 32>>>(x, y, B);
    rdl_fin<<<1, 1>>>(out, B);
}

// round 5
// speedup vs baseline: 1.9700x; 1.2139x over previous
#include <cuda_runtime.h>
#include <cuda_bf16.h>
#include <math.h>

#define FULLMASK 0xFFFFFFFFu
#define NW 4              // warps per block, one matrix per warp
#define BITERS 16         // bisection iterations (error floor is fp32 output ulp)

__device__ double g_acc = 0.0;
__device__ unsigned int g_cnt = 0;

__device__ __forceinline__ float warp_sum(float v) {
    v += __shfl_xor_sync(FULLMASK, v, 16);
    v += __shfl_xor_sync(FULLMASK, v, 8);
    v += __shfl_xor_sync(FULLMASK, v, 4);
    v += __shfl_xor_sync(FULLMASK, v, 2);
    v += __shfl_xor_sync(FULLMASK, v, 1);
    return v;
}

// raw approximate reciprocal: sign-correct (+-0 -> +-inf). Sturm needs signs only.
__device__ __forceinline__ float frcp(float x) {
    float r; asm("rcp.approx.f32 %0, %1;" : "=f"(r) : "f"(x)); return r;
}

__global__ __launch_bounds__(NW * 32, 5)
void rdl_main(const float* __restrict__ X, const float* __restrict__ Y,
              float* __restrict__ out, int B) {
    const int lane = threadIdx.x & 31;
    const int wid  = threadIdx.x >> 5;
    const int mat  = blockIdx.x * NW + wid;

    // Lsh rows 16B-aligned (stride 36) for float4 broadcast reads.
    __shared__ float Lsh[NW][32][36];
    __shared__ float Bs [NW][32][33];  // transpose buf; rows 0,4-5,8 reused (v / vw / e)
    __shared__ float wsum[NW];

    float contrib = 0.0f;

    if (mat < B) {
        const float* xb = X + (size_t)mat * 1024;
        const float* yb = Y + (size_t)mat * 1024;

        // ---- load Y column `lane` (== row, symmetric) ----
        float Lr[32];
        #pragma unroll
        for (int c = 0; c < 32; ++c) Lr[c] = yb[c * 32 + lane];

        // ---- Cholesky: row-k of L read back from smem as float4 broadcasts
        //      (written in earlier steps). Diag of Lsh holds 1/L[k][k]. ----
        #pragma unroll
        for (int k = 0; k < 32; ++k) {
            __syncwarp();
            float s0 = Lr[k], s1 = 0.f, s2 = 0.f, s3 = 0.f;
            #pragma unroll
            for (int g = 0; g * 4 < k; ++g) {
                float4 Lv = *(const float4*)&Lsh[wid][k][g * 4];
                if (g*4+0 < k) s0 = fmaf(-Lr[g*4+0], Lv.x, s0);
                if (g*4+1 < k) s1 = fmaf(-Lr[g*4+1], Lv.y, s1);
                if (g*4+2 < k) s2 = fmaf(-Lr[g*4+2], Lv.z, s2);
                if (g*4+3 < k) s3 = fmaf(-Lr[g*4+3], Lv.w, s3);
            }
            float s   = (s0 + s1) + (s2 + s3);
            float skk = __shfl_sync(FULLMASK, s, k);
            float inv = rsqrtf(skk);
            float val = (lane == k) ? inv : s * inv;
            Lr[k] = val;
            Lsh[wid][lane][k] = val;        // column store (upper-tri garbage never read)
        }
        __syncwarp();

        // ---- load X now (regs freed from prefetch; latency hidden by occupancy) ----
        float z[32];
        #pragma unroll
        for (int c = 0; c < 32; ++c) z[c] = xb[c * 32 + lane];

        // ---- forward solve L Z = X (thread = column). float4 broadcast rows of L. ----
        #pragma unroll
        for (int i = 0; i < 32; ++i) {
            float s = z[i];
            #pragma unroll
            for (int g = 0; g * 4 <= i; ++g) {
                float4 Lv = *(const float4*)&Lsh[wid][i][g * 4];
                if (g*4+0 < i) s = fmaf(-Lv.x, z[g*4+0], s); else if (g*4+0 == i) s *= Lv.x;
                if (g*4+1 < i) s = fmaf(-Lv.y, z[g*4+1], s); else if (g*4+1 == i) s *= Lv.y;
                if (g*4+2 < i) s = fmaf(-Lv.z, z[g*4+2], s); else if (g*4+2 == i) s *= Lv.z;
                if (g*4+3 < i) s = fmaf(-Lv.w, z[g*4+3], s); else if (g*4+3 == i) s *= Lv.w;
            }
            z[i] = s;
        }

        // ---- transpose Z ----
        #pragma unroll
        for (int i = 0; i < 32; ++i) Bs[wid][lane][i] = z[i];
        __syncwarp();

        // ---- forward solve L M = Z^T  ->  M = L^{-1} X L^{-T} ----
        float m[32];
        #pragma unroll
        for (int i = 0; i < 32; ++i) {
            float s = Bs[wid][i][lane];
            #pragma unroll
            for (int g = 0; g * 4 <= i; ++g) {
                float4 Lv = *(const float4*)&Lsh[wid][i][g * 4];
                if (g*4+0 < i) s = fmaf(-Lv.x, m[g*4+0], s); else if (g*4+0 == i) s *= Lv.x;
                if (g*4+1 < i) s = fmaf(-Lv.y, m[g*4+1], s); else if (g*4+1 == i) s *= Lv.y;
                if (g*4+2 < i) s = fmaf(-Lv.z, m[g*4+2], s); else if (g*4+2 == i) s *= Lv.z;
                if (g*4+3 < i) s = fmaf(-Lv.w, m[g*4+3], s); else if (g*4+3 == i) s *= Lv.w;
            }
            m[i] = s;
        }
        __syncwarp();

        // ---- Householder tridiag, range-limited trailing update. e -> smem. ----
        float*  v_sh = &Bs[wid][0][0];            // 16B aligned
        float2* vw   = (float2*)&Bs[wid][4][0];   // 16B aligned
        float*  e_sh = &Bs[wid][8][0];            // 16B aligned
        #pragma unroll
        for (int k = 0; k < 30; ++k) {
            float xk    = (lane > k) ? m[k] : 0.0f;
            float alpha = __shfl_sync(FULLMASK, m[k], k + 1);
            float sigma = warp_sum((lane > k + 1) ? xk * xk : 0.0f);

            float mu    = sqrtf(fmaf(alpha, alpha, sigma));
            float beta  = (alpha >= 0.0f) ? -mu : mu;
            float tau   = __fdividef(beta - alpha, beta);
            float scale = __fdividef(1.0f, alpha - beta);
            float v     = (lane == k + 1) ? 1.0f
                        : ((lane > k + 1) ? xk * scale : 0.0f);
            if (sigma <= 1e-12f) { beta = alpha; tau = 0.0f; v = 0.0f; }  // warp-uniform
            if (lane == 0) e_sh[k] = beta;
            v_sh[lane] = v;
            __syncwarp();

            // p = tau * A v  (4 indep accumulators; v_j==0 for j<=k makes over-read exact)
            float p0 = 0.f, p1 = 0.f, p2 = 0.f, p3 = 0.f;
            #pragma unroll
            for (int g = (k + 1) & ~3; g < 32; g += 4) {
                float4 vv = *(const float4*)&v_sh[g];
                p0 = fmaf(m[g+0], vv.x, p0);
                p1 = fmaf(m[g+1], vv.y, p1);
                p2 = fmaf(m[g+2], vv.z, p2);
                p3 = fmaf(m[g+3], vv.w, p3);
            }
            float p = ((p0 + p1) + (p2 + p3)) * tau;

            float dot = tau * warp_sum(p * v);
            float w   = fmaf(-0.5f * dot, v, p);
            vw[lane]  = make_float2(v, w);
            __syncwarp();

            // trailing update: A <- A - v w^T - w v^T  (2 columns per LDS.128)
            #pragma unroll
            for (int g = (k + 1) & ~1; g < 32; g += 2) {
                float4 t = *(const float4*)&vw[g];     // {v_g, w_g, v_g1, w_g1}
                m[g+0] = fmaf(-v, t.y, fmaf(-w, t.x, m[g+0]));
                m[g+1] = fmaf(-v, t.w, fmaf(-w, t.z, m[g+1]));
            }
        }
        {
            float e30 = __shfl_sync(FULLMASK, m[30], 31);
            if (lane == 0) e_sh[30] = e30;
        }
        __syncwarp();

        // ---- diagonal via shfl; e2 + Gershgorin from e_sh in one pass ----
        float d[32];
        #pragma unroll
        for (int i = 0; i < 32; ++i) d[i] = __shfl_sync(FULLMASK, m[i], i);

        float e2[31];
        float glo = 1e30f, ghi = -1e30f, prev = 0.0f;
        #pragma unroll
        for (int i = 0; i < 31; ++i) {
            float ev = e_sh[i];
            e2[i] = fmaxf(ev * ev, 1e-28f);
            float ae = fabsf(ev);
            float r  = prev + ae;
            glo = fminf(glo, d[i] - r);
            ghi = fmaxf(ghi, d[i] + r);
            prev = ae;
        }
        glo = fminf(glo, d[31] - prev);
        ghi = fmaxf(ghi, d[31] + prev);
        float span = ghi - glo;
        float lo = glo - 1e-4f * span - 1e-6f;
        float hi = ghi + 1e-4f * span + 1e-6f;

        // ---- Sturm bisection: lane j isolates j-th smallest eigenvalue ----
        #pragma unroll 1
        for (int it = 0; it < BITERS; ++it) {
            float mid = 0.5f * (lo + hi);
            float q   = d[0] - mid;
            int   c   = __float_as_int(q) >> 31;      // -1 per negative pivot
            #pragma unroll
            for (int i = 1; i < 32; ++i) {
                q  = fmaf(-e2[i - 1], frcp(q), d[i] - mid);
                c += __float_as_int(q) >> 31;
            }
            bool up = (c + lane >= 0);                // count(<mid) <= lane
            lo = up ? mid : lo;
            hi = up ? hi  : mid;
        }
        float lam = fmaxf(0.5f * (lo + hi), 1e-20f);
        float lg  = logf(lam);
        contrib   = sqrtf(warp_sum(lg * lg));
    }

    // ---- block reduce + last-block finalize (single-kernel, graph-friendly) ----
    if (lane == 0) wsum[wid] = contrib;
    __syncthreads();
    if (threadIdx.x == 0) {
        double s = ((double)wsum[0] + (double)wsum[1])
                 + ((double)wsum[2] + (double)wsum[3]);
        atomicAdd(&g_acc, s);
        __threadfence();
        unsigned t = atomicAdd(&g_cnt, 1u);
        if (t == gridDim.x - 1) {                     // last block: all adds visible
            __threadfence();
            out[0] = (float)(g_acc / (double)B);
            g_acc = 0.0;                              // reset for next graph replay
            g_cnt = 0u;
        }
    }
}

extern "C" void kernel_launch(void* const* d_in, const int* in_sizes, int n_in,
                              void* d_out, int out_size) {
    const float* x = (const float*)d_in[0];
    const float* y = (const float*)d_in[1];
    int B = in_sizes[0] / 1024;
    float* out = (float*)d_out;

    int blocks = (B + NW - 1) / NW;
    rdl_main<<<blocks, NW * 32>>>(x, y, out, B);
}